// round 11
// baseline (speedup 1.0000x reference)
#include <cuda_runtime.h>

typedef unsigned long long ull;
#define DEVINL __device__ __forceinline__

DEVINL ull pk(float lo, float hi) {
    ull r; asm("mov.b64 %0, {%1, %2};" : "=l"(r) : "f"(lo), "f"(hi)); return r;
}
DEVINL void upk(ull v, float& lo, float& hi) {
    asm("mov.b64 {%0, %1}, %2;" : "=f"(lo), "=f"(hi) : "l"(v));
}
DEVINL ull ffma2(ull a, ull b, ull c) {
    ull d; asm("fma.rn.f32x2 %0, %1, %2, %3;" : "=l"(d) : "l"(a), "l"(b), "l"(c)); return d;
}

// ---------- scratch (no allocs allowed -> device globals) ----------
__device__ float g_t1[32 * 16 * 128 * 128];   // conv1 raw
__device__ float g_t2[32 * 32 * 64 * 64];     // conv2 raw
__device__ float g_t3[32 * 32 * 64 * 64];     // conv3 raw (pre-bn3 z_e)
__device__ float g_t4[32 * 32 * 64 * 64];     // dec conv1 raw
__device__ float g_t5[32 * 16 * 128 * 128];   // convT1 raw
__device__ float g_s1[32];                    // [0:16) sum, [16:32) sumsq
__device__ float g_s2[64];
__device__ float g_s3[64];
__device__ float g_s4[64];
__device__ float g_s5[32];
// fallbacks if out_size doesn't hold the full 4-tensor concat
__device__ float g_zefb[32 * 32 * 64 * 64];
__device__ float g_zqfb[32 * 32 * 64 * 64];
__device__ float g_latfb[32 * 64 * 64];

#define WARP_RED2(s, q)                                 \
    _Pragma("unroll")                                   \
    for (int _o = 16; _o; _o >>= 1) {                   \
        s += __shfl_down_sync(0xffffffffu, s, _o);      \
        q += __shfl_down_sync(0xffffffffu, q, _o);      \
    }

// ---------- K0: zero stats ----------
__global__ void k_zero() {
    int t = threadIdx.x;
    if (t < 32)       g_s1[t] = 0.f;
    else if (t < 96)  g_s2[t - 32] = 0.f;
    else if (t < 160) g_s3[t - 96] = 0.f;
    else if (t < 224) g_s4[t - 160] = 0.f;
    else              g_s5[t - 224] = 0.f;
}

// ---------- K1: conv1 1->16, k4 s2 p1, 256->128, + stats1 ----------
__global__ void __launch_bounds__(256) k_conv1(const float* __restrict__ x,
                                               const float* __restrict__ w,
                                               const float* __restrict__ b) {
    __shared__ float ws[256];
    __shared__ float bs[16], bq[16];
    int t = threadIdx.x;
    ws[t] = w[t];
    if (t < 16) { bs[t] = 0.f; bq[t] = 0.f; }
    __syncthreads();
    int idx = blockIdx.x * 256 + t;
    int ox = idx & 127, oy = (idx >> 7) & 127, n = idx >> 14;
    const float* xin = x + ((size_t)n << 16);
    int iy0 = 2 * oy - 1, ix0 = 2 * ox - 1;
    float v[16];
#pragma unroll
    for (int ky = 0; ky < 4; ky++)
#pragma unroll
        for (int kx = 0; kx < 4; kx++) {
            int iy = iy0 + ky, ix = ix0 + kx;
            v[ky * 4 + kx] = (iy >= 0 && iy < 256 && ix >= 0 && ix < 256)
                                 ? xin[(iy << 8) + ix] : 0.f;
        }
    float* to = g_t1 + ((size_t)n << 18) + (oy << 7) + ox;
#pragma unroll
    for (int co = 0; co < 16; co++) {
        float a = b[co];
#pragma unroll
        for (int k = 0; k < 16; k++) a = fmaf(v[k], ws[co * 16 + k], a);
        to[(size_t)co << 14] = a;
        float s = a, q = a * a;
        WARP_RED2(s, q)
        if ((t & 31) == 0) { atomicAdd(&bs[co], s); atomicAdd(&bq[co], q); }
    }
    __syncthreads();
    if (t < 16)      atomicAdd(&g_s1[t], bs[t]);
    else if (t < 32) atomicAdd(&g_s1[t], bq[t - 16]);
}

// ---------- K2: bn1+relu -> conv2 16->32, k4 s2 p1, 128->64, + stats2 ----------
__global__ void __launch_bounds__(256) k_conv2(const float* __restrict__ w,
                                               const float* __restrict__ b,
                                               const float* __restrict__ gg,
                                               const float* __restrict__ be) {
    __shared__ ull ws[4096];                 // [ci][cp][tap], co-pairs packed
    __shared__ float sm[16], sr[16], sg[16], sb[16];
    __shared__ float bs[32], bq[32];
    int t = threadIdx.x;
    if (t < 16) {
        float m = g_s1[t] * (1.f / 524288.f);
        float var = g_s1[16 + t] * (1.f / 524288.f) - m * m;
        sm[t] = m; sr[t] = 1.0f / sqrtf(var + 1e-5f);
        sg[t] = gg[t]; sb[t] = be[t];
    }
    if (t < 32) { bs[t] = 0.f; bq[t] = 0.f; }
    for (int e = t; e < 4096; e += 256) {
        int tap = e & 15, cp = (e >> 4) & 15, ci = e >> 8;
        ws[e] = pk(w[(2 * cp) * 256 + ci * 16 + tap],
                   w[(2 * cp + 1) * 256 + ci * 16 + tap]);
    }
    __syncthreads();
    int idx = blockIdx.x * 256 + t;
    int ox = idx & 63, oy = (idx >> 6) & 63, n = idx >> 12;
    int iy0 = 2 * oy - 1, ix0 = 2 * ox - 1;
    ull acc[16];
#pragma unroll
    for (int cp = 0; cp < 16; cp++) acc[cp] = pk(b[2 * cp], b[2 * cp + 1]);
#pragma unroll 1
    for (int ci = 0; ci < 16; ci++) {
        const float* tin = g_t1 + ((size_t)(n * 16 + ci) << 14);
        float m = sm[ci], r = sr[ci], g = sg[ci], bb = sb[ci];
        ull vp[16];
#pragma unroll
        for (int ky = 0; ky < 4; ky++)
#pragma unroll
            for (int kx = 0; kx < 4; kx++) {
                int iy = iy0 + ky, ix = ix0 + kx;
                float vv = 0.f;
                if (iy >= 0 && iy < 128 && ix >= 0 && ix < 128) {
                    float raw = tin[(iy << 7) + ix];
                    float bn = __fadd_rn(__fmul_rn(__fmul_rn(g, __fsub_rn(raw, m)), r), bb);
                    vv = fmaxf(bn, 0.f);
                }
                vp[ky * 4 + kx] = pk(vv, vv);
            }
        const ull* wb = ws + (ci << 8);
#pragma unroll
        for (int cp = 0; cp < 16; cp++) {
            const ulonglong2* qw = (const ulonglong2*)(wb + (cp << 4));
#pragma unroll
            for (int rr = 0; rr < 8; rr++) {
                ulonglong2 a2 = qw[rr];
                acc[cp] = ffma2(vp[2 * rr], a2.x, acc[cp]);
                acc[cp] = ffma2(vp[2 * rr + 1], a2.y, acc[cp]);
            }
        }
    }
    float* to = g_t2 + ((size_t)n << 17) + (oy << 6) + ox;
#pragma unroll
    for (int cp = 0; cp < 16; cp++) {
        float a0, a1; upk(acc[cp], a0, a1);
        to[(size_t)(2 * cp) << 12] = a0;
        to[(size_t)(2 * cp + 1) << 12] = a1;
        float s0 = a0, q0 = a0 * a0, s1 = a1, q1 = a1 * a1;
        WARP_RED2(s0, q0)
        WARP_RED2(s1, q1)
        if ((t & 31) == 0) {
            atomicAdd(&bs[2 * cp], s0);     atomicAdd(&bq[2 * cp], q0);
            atomicAdd(&bs[2 * cp + 1], s1); atomicAdd(&bq[2 * cp + 1], q1);
        }
    }
    __syncthreads();
    if (t < 32)      atomicAdd(&g_s2[t], bs[t]);
    else if (t < 64) atomicAdd(&g_s2[t], bq[t - 32]);
}

// ---------- K3: bn2+relu -> conv3 1x1 32->32, + stats3 ----------
__global__ void __launch_bounds__(256) k_conv1x1a(const float* __restrict__ w,
                                                  const float* __restrict__ b,
                                                  const float* __restrict__ gg,
                                                  const float* __restrict__ be) {
    __shared__ ull ws[512];                  // [ci][cp]
    __shared__ float sm[32], sr[32], sg[32], sb[32];
    __shared__ float bs[32], bq[32];
    int t = threadIdx.x;
    if (t < 32) {
        float m = g_s2[t] * (1.f / 131072.f);
        float var = g_s2[32 + t] * (1.f / 131072.f) - m * m;
        sm[t] = m; sr[t] = 1.0f / sqrtf(var + 1e-5f);
        sg[t] = gg[t]; sb[t] = be[t];
        bs[t] = 0.f; bq[t] = 0.f;
    }
    for (int e = t; e < 512; e += 256) {
        int cp = e & 15, ci = e >> 4;
        ws[e] = pk(w[(2 * cp) * 32 + ci], w[(2 * cp + 1) * 32 + ci]);
    }
    __syncthreads();
    int pos = blockIdx.x * 256 + t;          // 131072 positions
    int xy = pos & 4095, n = pos >> 12;
    ull acc[16];
#pragma unroll
    for (int cp = 0; cp < 16; cp++) acc[cp] = pk(b[2 * cp], b[2 * cp + 1]);
#pragma unroll 4
    for (int ci = 0; ci < 32; ci++) {
        float raw = g_t2[(((size_t)(n << 5) + ci) << 12) + xy];
        float bn = __fadd_rn(__fmul_rn(__fmul_rn(sg[ci], __fsub_rn(raw, sm[ci])), sr[ci]), sb[ci]);
        float vv = fmaxf(bn, 0.f);
        ull vp = pk(vv, vv);
        const ull* wb = ws + (ci << 4);
#pragma unroll
        for (int cp = 0; cp < 16; cp++) acc[cp] = ffma2(vp, wb[cp], acc[cp]);
    }
    float* to = g_t3 + ((size_t)n << 17) + xy;
#pragma unroll
    for (int cp = 0; cp < 16; cp++) {
        float a0, a1; upk(acc[cp], a0, a1);
        to[(size_t)(2 * cp) << 12] = a0;
        to[(size_t)(2 * cp + 1) << 12] = a1;
        float s0 = a0, q0 = a0 * a0, s1 = a1, q1 = a1 * a1;
        WARP_RED2(s0, q0)
        WARP_RED2(s1, q1)
        if ((t & 31) == 0) {
            atomicAdd(&bs[2 * cp], s0);     atomicAdd(&bq[2 * cp], q0);
            atomicAdd(&bs[2 * cp + 1], s1); atomicAdd(&bq[2 * cp + 1], q1);
        }
    }
    __syncthreads();
    if (t < 32)      atomicAdd(&g_s3[t], bs[t]);
    else if (t < 64) atomicAdd(&g_s3[t], bq[t - 32]);
}

// ---------- K4: bn3 -> z_e, VQ argmin -> latents, z_q, dec conv1 1x1 + stats4 ----------
__global__ void __launch_bounds__(256) k_vq(const float* __restrict__ emb,
                                            const float* __restrict__ gg,
                                            const float* __restrict__ be,
                                            const float* __restrict__ dw,
                                            const float* __restrict__ db,
                                            float* __restrict__ ze,
                                            float* __restrict__ zq,
                                            float* __restrict__ lat) {
    extern __shared__ unsigned char smraw[];
    ull* pe  = (ull*)smraw;          // 8192: [pair p][k] = (emb[2p][k], emb[2p+1][k])
    ull* pE  = pe + 8192;            // 256 : (|e_{2p}|^2, |e_{2p+1}|^2)
    ull* dwp = pE + 256;             // 512 : dec conv1 weight pairs [ci][cp]
    ull* dbp = dwp + 512;            // 16  : dec conv1 bias pairs
    float* sm3 = (float*)(dbp + 16);
    float* sr3 = sm3 + 32; float* sg3 = sr3 + 32; float* sb3 = sg3 + 32;
    float* bs = sb3 + 32; float* bq = bs + 32;
    int t = threadIdx.x;

    for (int e = t; e < 8192; e += 256) {
        int k = e & 31, p = e >> 5;
        pe[e] = pk(emb[(2 * p) * 32 + k], emb[(2 * p + 1) * 32 + k]);
    }
    {   // E_i = sum_k emb[i][k]^2, sequential mul+add (replicates ref structure)
        int p = t;                    // t < 256 always
        float e0 = 0.f, e1 = 0.f;
#pragma unroll 8
        for (int k = 0; k < 32; k++) {
            float a = emb[(2 * p) * 32 + k];
            float c = emb[(2 * p + 1) * 32 + k];
            e0 = __fadd_rn(e0, __fmul_rn(a, a));
            e1 = __fadd_rn(e1, __fmul_rn(c, c));
        }
        pE[p] = pk(e0, e1);
    }
    for (int e = t; e < 512; e += 256) {
        int cp = e & 15, ci = e >> 4;
        dwp[e] = pk(dw[(2 * cp) * 32 + ci], dw[(2 * cp + 1) * 32 + ci]);
    }
    if (t < 16) dbp[t] = pk(db[2 * t], db[2 * t + 1]);
    if (t < 32) {
        float m = g_s3[t] * (1.f / 131072.f);
        float var = g_s3[32 + t] * (1.f / 131072.f) - m * m;
        sm3[t] = m; sr3[t] = 1.0f / sqrtf(var + 1e-5f);
        sg3[t] = gg[t]; sb3[t] = be[t];
        bs[t] = 0.f; bq[t] = 0.f;
    }
    __syncthreads();

    int pos = blockIdx.x * 256 + t;   // 131072 positions
    int xy = pos & 4095, n = pos >> 12;

    ull zp[32];
    float S = 0.f;
#pragma unroll
    for (int k = 0; k < 32; k++) {
        float raw = g_t3[(((size_t)(n << 5) + k) << 12) + xy];
        float zb = __fadd_rn(__fmul_rn(__fmul_rn(sg3[k], __fsub_rn(raw, sm3[k])), sr3[k]), sb3[k]);
        ze[(((size_t)(n << 5) + k) << 12) + xy] = zb;
        S = __fadd_rn(S, __fmul_rn(zb, zb));
        zp[k] = pk(zb, zb);
    }

    float best = 3.402823466e38f;
    int bi = 0;
#pragma unroll 1
    for (int q = 0; q < 256; q += 2) {
        const ulonglong2* e0 = (const ulonglong2*)(pe + (q << 5));
        const ulonglong2* e1 = (const ulonglong2*)(pe + ((q + 1) << 5));
        ull a0 = 0ull, a1 = 0ull;
#pragma unroll
        for (int kk = 0; kk < 16; kk++) {
            ulonglong2 w0 = e0[kk];
            ulonglong2 w1 = e1[kk];
            a0 = ffma2(zp[2 * kk], w0.x, a0);
            a1 = ffma2(zp[2 * kk], w1.x, a1);
            a0 = ffma2(zp[2 * kk + 1], w0.y, a0);
            a1 = ffma2(zp[2 * kk + 1], w1.y, a1);
        }
        float m0, m1, m2, m3, E0, E1, E2, E3;
        upk(a0, m0, m1); upk(a1, m2, m3);
        upk(pE[q], E0, E1); upk(pE[q + 1], E2, E3);
        float d;
        d = __fadd_rn(__fsub_rn(S, __fadd_rn(m0, m0)), E0); if (d < best) { best = d; bi = 2 * q; }
        d = __fadd_rn(__fsub_rn(S, __fadd_rn(m1, m1)), E1); if (d < best) { best = d; bi = 2 * q + 1; }
        d = __fadd_rn(__fsub_rn(S, __fadd_rn(m2, m2)), E2); if (d < best) { best = d; bi = 2 * q + 2; }
        d = __fadd_rn(__fsub_rn(S, __fadd_rn(m3, m3)), E3); if (d < best) { best = d; bi = 2 * q + 3; }
    }

    lat[pos] = (float)bi;

    // z_q gather + dec conv1 (1x1, 32->32)
    const float* pef = (const float*)pe;
    int zbase = (((bi >> 1) << 5) << 1) + (bi & 1);   // ((bi>>1)*32 + k)*2 + (bi&1)
    ull acc[16];
#pragma unroll
    for (int cp = 0; cp < 16; cp++) acc[cp] = dbp[cp];
#pragma unroll 4
    for (int ci = 0; ci < 32; ci++) {
        float zv = pef[zbase + (ci << 1)];
        zq[(((size_t)(n << 5) + ci) << 12) + xy] = zv;
        ull vp = pk(zv, zv);
        const ull* wb = dwp + (ci << 4);
#pragma unroll
        for (int cp = 0; cp < 16; cp++) acc[cp] = ffma2(vp, wb[cp], acc[cp]);
    }
    float* to = g_t4 + ((size_t)n << 17) + xy;
#pragma unroll
    for (int cp = 0; cp < 16; cp++) {
        float a0, a1; upk(acc[cp], a0, a1);
        to[(size_t)(2 * cp) << 12] = a0;
        to[(size_t)(2 * cp + 1) << 12] = a1;
        float s0 = a0, q0 = a0 * a0, s1 = a1, q1 = a1 * a1;
        WARP_RED2(s0, q0)
        WARP_RED2(s1, q1)
        if ((t & 31) == 0) {
            atomicAdd(&bs[2 * cp], s0);     atomicAdd(&bq[2 * cp], q0);
            atomicAdd(&bs[2 * cp + 1], s1); atomicAdd(&bq[2 * cp + 1], q1);
        }
    }
    __syncthreads();
    if (t < 32)      atomicAdd(&g_s4[t], bs[t]);
    else if (t < 64) atomicAdd(&g_s4[t], bq[t - 32]);
}

// ---------- K5: bn4+relu -> convT1 32->16 (k4 s2 p1, 64->128), + stats5 ----------
__global__ void __launch_bounds__(256) k_convT1(const float* __restrict__ w,
                                                const float* __restrict__ b,
                                                const float* __restrict__ gg,
                                                const float* __restrict__ be) {
    __shared__ ull wp[4096];                 // [ci][tap][cp] co-pairs, ci<32, cp<8
    __shared__ ull bp[8];
    __shared__ float sm[32], sr[32], sg[32], sb[32];
    __shared__ float bs[16], bq[16];
    int t = threadIdx.x;
    if (t < 32) {
        float m = g_s4[t] * (1.f / 131072.f);
        float var = g_s4[32 + t] * (1.f / 131072.f) - m * m;
        sm[t] = m; sr[t] = 1.0f / sqrtf(var + 1e-5f);
        sg[t] = gg[t]; sb[t] = be[t];
    }
    if (t < 16) { bs[t] = 0.f; bq[t] = 0.f; }
    if (t < 8)  bp[t] = pk(b[2 * t], b[2 * t + 1]);
    for (int e = t; e < 4096; e += 256) {
        int cp = e & 7, tap = (e >> 3) & 15, ci = e >> 7;
        // dtw1 layout (Cin=32, Cout=16, 4, 4): ci*256 + co*16 + tap
        wp[e] = pk(w[ci * 256 + (2 * cp) * 16 + tap],
                   w[ci * 256 + (2 * cp + 1) * 16 + tap]);
    }
    __syncthreads();
    int idx = blockIdx.x * 256 + t;          // 524288 output pixels
    int ox = idx & 127, oy = (idx >> 7) & 127, n = idx >> 14;
    int iya = (oy + 1) >> 1, kya = oy - 2 * iya + 1, iyb = iya - 1, kyb = kya + 2;
    int ixa = (ox + 1) >> 1, kxa = ox - 2 * ixa + 1, ixb = ixa - 1, kxb = kxa + 2;
    bool vya = iya <= 63, vyb = iyb >= 0, vxa = ixa <= 63, vxb = ixb >= 0;
    int taa = kya * 4 + kxa, tab = kya * 4 + kxb, tba = kyb * 4 + kxa, tbb = kyb * 4 + kxb;
    ull acc[8];
#pragma unroll
    for (int cp = 0; cp < 8; cp++) acc[cp] = bp[cp];
#pragma unroll 1
    for (int ci = 0; ci < 32; ci++) {
        const float* tin = g_t4 + (((size_t)(n << 5) + ci) << 12);
        float m = sm[ci], r = sr[ci], g = sg[ci], bb = sb[ci];
        float f00 = 0.f, f01 = 0.f, f10 = 0.f, f11 = 0.f;
        if (vya && vxa) f00 = fmaxf(__fadd_rn(__fmul_rn(__fmul_rn(g, __fsub_rn(tin[(iya << 6) + ixa], m)), r), bb), 0.f);
        if (vya && vxb) f01 = fmaxf(__fadd_rn(__fmul_rn(__fmul_rn(g, __fsub_rn(tin[(iya << 6) + ixb], m)), r), bb), 0.f);
        if (vyb && vxa) f10 = fmaxf(__fadd_rn(__fmul_rn(__fmul_rn(g, __fsub_rn(tin[(iyb << 6) + ixa], m)), r), bb), 0.f);
        if (vyb && vxb) f11 = fmaxf(__fadd_rn(__fmul_rn(__fmul_rn(g, __fsub_rn(tin[(iyb << 6) + ixb], m)), r), bb), 0.f);
        ull p00 = pk(f00, f00), p01 = pk(f01, f01), p10 = pk(f10, f10), p11 = pk(f11, f11);
        const ull* wb0 = wp + (ci << 7);
        const ulonglong2* wA = (const ulonglong2*)(wb0 + (taa << 3));
        const ulonglong2* wB = (const ulonglong2*)(wb0 + (tab << 3));
        const ulonglong2* wC = (const ulonglong2*)(wb0 + (tba << 3));
        const ulonglong2* wD = (const ulonglong2*)(wb0 + (tbb << 3));
#pragma unroll
        for (int j = 0; j < 4; j++) {
            ulonglong2 a2 = wA[j], b2 = wB[j], c2 = wC[j], d2 = wD[j];
            acc[2 * j]     = ffma2(p00, a2.x, acc[2 * j]);
            acc[2 * j + 1] = ffma2(p00, a2.y, acc[2 * j + 1]);
            acc[2 * j]     = ffma2(p01, b2.x, acc[2 * j]);
            acc[2 * j + 1] = ffma2(p01, b2.y, acc[2 * j + 1]);
            acc[2 * j]     = ffma2(p10, c2.x, acc[2 * j]);
            acc[2 * j + 1] = ffma2(p10, c2.y, acc[2 * j + 1]);
            acc[2 * j]     = ffma2(p11, d2.x, acc[2 * j]);
            acc[2 * j + 1] = ffma2(p11, d2.y, acc[2 * j + 1]);
        }
    }
    float* to = g_t5 + ((size_t)n << 18) + (oy << 7) + ox;
#pragma unroll
    for (int cp = 0; cp < 8; cp++) {
        float a0, a1; upk(acc[cp], a0, a1);
        to[(size_t)(2 * cp) << 14] = a0;
        to[(size_t)(2 * cp + 1) << 14] = a1;
        float s0 = a0, q0 = a0 * a0, s1 = a1, q1 = a1 * a1;
        WARP_RED2(s0, q0)
        WARP_RED2(s1, q1)
        if ((t & 31) == 0) {
            atomicAdd(&bs[2 * cp], s0);     atomicAdd(&bq[2 * cp], q0);
            atomicAdd(&bs[2 * cp + 1], s1); atomicAdd(&bq[2 * cp + 1], q1);
        }
    }
    __syncthreads();
    if (t < 16)      atomicAdd(&g_s5[t], bs[t]);
    else if (t < 32) atomicAdd(&g_s5[t], bq[t - 16]);
}

// ---------- K6: bn5+relu -> convT2 16->30 (k4 s2 p1, 128->256) -> x_tilde ----------
__global__ void __launch_bounds__(256) k_convT2(const float* __restrict__ w,
                                                const float* __restrict__ b,
                                                const float* __restrict__ gg,
                                                const float* __restrict__ be,
                                                float* __restrict__ out) {
    __shared__ ull wp[4096];                 // [ci][tap][cp16] ci<16, cp padded to 16
    __shared__ ull bp[16];
    __shared__ float sm[16], sr[16], sg[16], sb[16];
    int t = threadIdx.x;
    if (t < 16) {
        float m = g_s5[t] * (1.f / 524288.f);
        float var = g_s5[16 + t] * (1.f / 524288.f) - m * m;
        sm[t] = m; sr[t] = 1.0f / sqrtf(var + 1e-5f);
        sg[t] = gg[t]; sb[t] = be[t];
    }
    if (t < 16) bp[t] = (t < 15) ? pk(b[2 * t], b[2 * t + 1]) : pk(0.f, 0.f);
    for (int e = t; e < 4096; e += 256) {
        int cp = e & 15, tap = (e >> 4) & 15, ci = e >> 8;
        // dtw2 layout (Cin=16, Cout=30, 4, 4): ci*480 + co*16 + tap; cp=15 is zero pad
        wp[e] = (cp < 15) ? pk(w[ci * 480 + (2 * cp) * 16 + tap],
                               w[ci * 480 + (2 * cp + 1) * 16 + tap])
                          : pk(0.f, 0.f);
    }
    __syncthreads();
    int idx = blockIdx.x * 256 + t;          // 2097152 output pixels
    int ox = idx & 255, oy = (idx >> 8) & 255, n = idx >> 16;
    int iya = (oy + 1) >> 1, kya = oy - 2 * iya + 1, iyb = iya - 1, kyb = kya + 2;
    int ixa = (ox + 1) >> 1, kxa = ox - 2 * ixa + 1, ixb = ixa - 1, kxb = kxa + 2;
    bool vya = iya <= 127, vyb = iyb >= 0, vxa = ixa <= 127, vxb = ixb >= 0;
    int taa = kya * 4 + kxa, tab = kya * 4 + kxb, tba = kyb * 4 + kxa, tbb = kyb * 4 + kxb;
    ull acc[16];
#pragma unroll
    for (int cp = 0; cp < 16; cp++) acc[cp] = bp[cp];
#pragma unroll 1
    for (int ci = 0; ci < 16; ci++) {
        const float* tin = g_t5 + (((size_t)(n << 4) + ci) << 14);
        float m = sm[ci], r = sr[ci], g = sg[ci], bb = sb[ci];
        float f00 = 0.f, f01 = 0.f, f10 = 0.f, f11 = 0.f;
        if (vya && vxa) f00 = fmaxf(__fadd_rn(__fmul_rn(__fmul_rn(g, __fsub_rn(tin[(iya << 7) + ixa], m)), r), bb), 0.f);
        if (vya && vxb) f01 = fmaxf(__fadd_rn(__fmul_rn(__fmul_rn(g, __fsub_rn(tin[(iya << 7) + ixb], m)), r), bb), 0.f);
        if (vyb && vxa) f10 = fmaxf(__fadd_rn(__fmul_rn(__fmul_rn(g, __fsub_rn(tin[(iyb << 7) + ixa], m)), r), bb), 0.f);
        if (vyb && vxb) f11 = fmaxf(__fadd_rn(__fmul_rn(__fmul_rn(g, __fsub_rn(tin[(iyb << 7) + ixb], m)), r), bb), 0.f);
        ull p00 = pk(f00, f00), p01 = pk(f01, f01), p10 = pk(f10, f10), p11 = pk(f11, f11);
        const ull* wb0 = wp + (ci << 8);
        const ulonglong2* wA = (const ulonglong2*)(wb0 + (taa << 4));
        const ulonglong2* wB = (const ulonglong2*)(wb0 + (tab << 4));
        const ulonglong2* wC = (const ulonglong2*)(wb0 + (tba << 4));
        const ulonglong2* wD = (const ulonglong2*)(wb0 + (tbb << 4));
#pragma unroll
        for (int j = 0; j < 8; j++) {
            ulonglong2 a2 = wA[j], b2 = wB[j], c2 = wC[j], d2 = wD[j];
            acc[2 * j]     = ffma2(p00, a2.x, acc[2 * j]);
            acc[2 * j + 1] = ffma2(p00, a2.y, acc[2 * j + 1]);
            acc[2 * j]     = ffma2(p01, b2.x, acc[2 * j]);
            acc[2 * j + 1] = ffma2(p01, b2.y, acc[2 * j + 1]);
            acc[2 * j]     = ffma2(p10, c2.x, acc[2 * j]);
            acc[2 * j + 1] = ffma2(p10, c2.y, acc[2 * j + 1]);
            acc[2 * j]     = ffma2(p11, d2.x, acc[2 * j]);
            acc[2 * j + 1] = ffma2(p11, d2.y, acc[2 * j + 1]);
        }
    }
    float* to = out + (size_t)n * (30 * 65536) + (oy << 8) + ox;
#pragma unroll
    for (int cp = 0; cp < 15; cp++) {
        float a0, a1; upk(acc[cp], a0, a1);
        to[(size_t)(2 * cp) << 16] = a0;
        to[(size_t)(2 * cp + 1) << 16] = a1;
    }
}

// ---------- host ----------
extern "C" void kernel_launch(void* const* d_in, const int* in_sizes, int n_in,
                              void* d_out, int out_size) {
    const float* x    = (const float*)d_in[0];
    const float* w1   = (const float*)d_in[1];
    const float* b1   = (const float*)d_in[2];
    const float* g1   = (const float*)d_in[3];
    const float* be1  = (const float*)d_in[4];
    const float* w2   = (const float*)d_in[5];
    const float* b2   = (const float*)d_in[6];
    const float* g2   = (const float*)d_in[7];
    const float* be2  = (const float*)d_in[8];
    const float* w3   = (const float*)d_in[9];
    const float* b3   = (const float*)d_in[10];
    const float* g3   = (const float*)d_in[11];
    const float* be3  = (const float*)d_in[12];
    const float* emb  = (const float*)d_in[13];
    const float* dw1  = (const float*)d_in[14];
    const float* db1  = (const float*)d_in[15];
    const float* dg1  = (const float*)d_in[16];
    const float* dbe1 = (const float*)d_in[17];
    const float* dtw1 = (const float*)d_in[18];
    const float* dtb1 = (const float*)d_in[19];
    const float* dg2  = (const float*)d_in[20];
    const float* dbe2 = (const float*)d_in[21];
    const float* dtw2 = (const float*)d_in[22];
    const float* dtb2 = (const float*)d_in[23];

    float* out = (float*)d_out;
    const long long XT = 62914560LL, ZE = 4194304LL, LA = 131072LL;
    float *xt = out, *ze, *zq, *lat;
    if ((long long)out_size >= XT + 2 * ZE + LA) {
        ze  = out + XT;
        zq  = out + XT + ZE;
        lat = out + XT + 2 * ZE;
    } else {
        void* p;
        cudaGetSymbolAddress(&p, g_zefb);  ze  = (float*)p;
        cudaGetSymbolAddress(&p, g_zqfb);  zq  = (float*)p;
        cudaGetSymbolAddress(&p, g_latfb); lat = (float*)p;
    }

    cudaFuncSetAttribute(k_vq, cudaFuncAttributeMaxDynamicSharedMemorySize, 73728);

    k_zero<<<1, 256>>>();
    k_conv1<<<2048, 256>>>(x, w1, b1);
    k_conv2<<<512, 256>>>(w2, b2, g1, be1);
    k_conv1x1a<<<512, 256>>>(w3, b3, g2, be2);
    k_vq<<<512, 256, 73728>>>(emb, g3, be3, dw1, db1, ze, zq, lat);
    k_convT1<<<2048, 256>>>(dtw1, dtb1, dg1, dbe1);
    k_convT2<<<8192, 256>>>(dtw2, dtb2, dg2, dbe2, xt);
}

// round 17
// speedup vs baseline: 1.0447x; 1.0447x over previous
#include <cuda_runtime.h>

typedef unsigned long long ull;
#define DEVINL __device__ __forceinline__

DEVINL ull pk(float lo, float hi) {
    ull r; asm("mov.b64 %0, {%1, %2};" : "=l"(r) : "f"(lo), "f"(hi)); return r;
}
DEVINL void upk(ull v, float& lo, float& hi) {
    asm("mov.b64 {%0, %1}, %2;" : "=f"(lo), "=f"(hi) : "l"(v));
}
DEVINL ull ffma2(ull a, ull b, ull c) {
    ull d; asm("fma.rn.f32x2 %0, %1, %2, %3;" : "=l"(d) : "l"(a), "l"(b), "l"(c)); return d;
}
DEVINL float bnrelu(float raw, float g, float m, float r, float bb) {
    return fmaxf(__fadd_rn(__fmul_rn(__fmul_rn(g, __fsub_rn(raw, m)), r), bb), 0.f);
}

// ---------- scratch ----------
__device__ float g_t1[32 * 16 * 128 * 128];
__device__ float g_t2[32 * 32 * 64 * 64];
__device__ float g_t3[32 * 32 * 64 * 64];
__device__ float g_t4[32 * 32 * 64 * 64];
__device__ float g_t5[32 * 16 * 128 * 128];
__device__ float g_s1[32];
__device__ float g_s2[64];
__device__ float g_s3[64];
__device__ float g_s4[64];
__device__ float g_s5[32];
__device__ float g_zefb[32 * 32 * 64 * 64];
__device__ float g_zqfb[32 * 32 * 64 * 64];
__device__ float g_latfb[32 * 64 * 64];

#define WARP_RED2(s, q)                                 \
    _Pragma("unroll")                                   \
    for (int _o = 16; _o; _o >>= 1) {                   \
        s += __shfl_down_sync(0xffffffffu, s, _o);      \
        q += __shfl_down_sync(0xffffffffu, q, _o);      \
    }

// ---------- K0 ----------
__global__ void k_zero() {
    int t = threadIdx.x;
    if (t < 32)       g_s1[t] = 0.f;
    else if (t < 96)  g_s2[t - 32] = 0.f;
    else if (t < 160) g_s3[t - 96] = 0.f;
    else if (t < 224) g_s4[t - 160] = 0.f;
    else              g_s5[t - 224] = 0.f;
}

// ---------- K1: conv1 1->16, + stats1 ----------
__global__ void __launch_bounds__(256) k_conv1(const float* __restrict__ x,
                                               const float* __restrict__ w,
                                               const float* __restrict__ b) {
    __shared__ float ws[256];
    __shared__ float bs[16], bq[16];
    int t = threadIdx.x;
    ws[t] = w[t];
    if (t < 16) { bs[t] = 0.f; bq[t] = 0.f; }
    __syncthreads();
    int idx = blockIdx.x * 256 + t;
    int ox = idx & 127, oy = (idx >> 7) & 127, n = idx >> 14;
    const float* xin = x + ((size_t)n << 16);
    int iy0 = 2 * oy - 1, ix0 = 2 * ox - 1;
    float v[16];
#pragma unroll
    for (int ky = 0; ky < 4; ky++)
#pragma unroll
        for (int kx = 0; kx < 4; kx++) {
            int iy = iy0 + ky, ix = ix0 + kx;
            v[ky * 4 + kx] = (iy >= 0 && iy < 256 && ix >= 0 && ix < 256)
                                 ? xin[(iy << 8) + ix] : 0.f;
        }
    float* to = g_t1 + ((size_t)n << 18) + (oy << 7) + ox;
#pragma unroll
    for (int co = 0; co < 16; co++) {
        float a = b[co];
#pragma unroll
        for (int k = 0; k < 16; k++) a = fmaf(v[k], ws[co * 16 + k], a);
        to[(size_t)co << 14] = a;
        float s = a, q = a * a;
        WARP_RED2(s, q)
        if ((t & 31) == 0) { atomicAdd(&bs[co], s); atomicAdd(&bq[co], q); }
    }
    __syncthreads();
    if (t < 16)      atomicAdd(&g_s1[t], bs[t]);
    else if (t < 32) atomicAdd(&g_s1[t], bq[t - 16]);
}

// ---------- K2: bn1+relu -> conv2, split cp (8 pairs/block), + stats2 ----------
__global__ void __launch_bounds__(256) k_conv2(const float* __restrict__ w,
                                               const float* __restrict__ b,
                                               const float* __restrict__ gg,
                                               const float* __restrict__ be) {
    __shared__ ull ws2[2048];                // [ci][cpl(8)][tap(16)]
    __shared__ float sm[16], sr[16], sg[16], sb[16];
    __shared__ float bs[16], bq[16];
    int t = threadIdx.x;
    int blk = blockIdx.x;
    int h = blk >> 9;                        // 0 or 1: cp half
    if (t < 16) {
        float m = g_s1[t] * (1.f / 524288.f);
        float var = g_s1[16 + t] * (1.f / 524288.f) - m * m;
        sm[t] = m; sr[t] = 1.0f / sqrtf(var + 1e-5f);
        sg[t] = gg[t]; sb[t] = be[t];
        bs[t] = 0.f; bq[t] = 0.f;
    }
    for (int e = t; e < 2048; e += 256) {
        int tap = e & 15, cpl = (e >> 4) & 7, ci = e >> 7;
        int co = 2 * (8 * h + cpl);
        ws2[e] = pk(w[co * 256 + ci * 16 + tap], w[(co + 1) * 256 + ci * 16 + tap]);
    }
    __syncthreads();
    int idx = (blk & 511) * 256 + t;
    int ox = idx & 63, oy = (idx >> 6) & 63, n = idx >> 12;
    int iy0 = 2 * oy - 1, ix0 = 2 * ox - 1;
    ull acc[8];
#pragma unroll
    for (int cpl = 0; cpl < 8; cpl++)
        acc[cpl] = pk(b[2 * (8 * h + cpl)], b[2 * (8 * h + cpl) + 1]);
#pragma unroll 1
    for (int ci = 0; ci < 16; ci++) {
        const float* tin = g_t1 + ((size_t)(n * 16 + ci) << 14);
        float m = sm[ci], r = sr[ci], g = sg[ci], bb = sb[ci];
        ull vp[16];
#pragma unroll
        for (int ky = 0; ky < 4; ky++)
#pragma unroll
            for (int kx = 0; kx < 4; kx++) {
                int iy = iy0 + ky, ix = ix0 + kx;
                float vv = 0.f;
                if (iy >= 0 && iy < 128 && ix >= 0 && ix < 128)
                    vv = bnrelu(tin[(iy << 7) + ix], g, m, r, bb);
                vp[ky * 4 + kx] = pk(vv, vv);
            }
        const ull* wb = ws2 + (ci << 7);
#pragma unroll
        for (int cpl = 0; cpl < 8; cpl++) {
            const ulonglong2* qw = (const ulonglong2*)(wb + (cpl << 4));
#pragma unroll
            for (int rr = 0; rr < 8; rr++) {
                ulonglong2 a2 = qw[rr];
                acc[cpl] = ffma2(vp[2 * rr], a2.x, acc[cpl]);
                acc[cpl] = ffma2(vp[2 * rr + 1], a2.y, acc[cpl]);
            }
        }
    }
    float* to = g_t2 + ((size_t)n << 17) + (oy << 6) + ox;
#pragma unroll
    for (int cpl = 0; cpl < 8; cpl++) {
        int co = 2 * (8 * h + cpl);
        float a0, a1; upk(acc[cpl], a0, a1);
        to[(size_t)co << 12] = a0;
        to[(size_t)(co + 1) << 12] = a1;
        float s0 = a0, q0 = a0 * a0, s1 = a1, q1 = a1 * a1;
        WARP_RED2(s0, q0)
        WARP_RED2(s1, q1)
        if ((t & 31) == 0) {
            atomicAdd(&bs[2 * cpl], s0);     atomicAdd(&bq[2 * cpl], q0);
            atomicAdd(&bs[2 * cpl + 1], s1); atomicAdd(&bq[2 * cpl + 1], q1);
        }
    }
    __syncthreads();
    if (t < 16)      atomicAdd(&g_s2[16 * h + t], bs[t]);
    else if (t < 32) atomicAdd(&g_s2[32 + 16 * h + (t - 16)], bq[t - 16]);
}

// ---------- K3: bn2+relu -> conv3 1x1, split cp, batched loads, + stats3 ----------
__global__ void __launch_bounds__(256) k_conv1x1a(const float* __restrict__ w,
                                                  const float* __restrict__ b,
                                                  const float* __restrict__ gg,
                                                  const float* __restrict__ be) {
    __shared__ ull ws2[256];                 // [ci][cpl(8)]
    __shared__ float sm[32], sr[32], sg[32], sb[32];
    __shared__ float bs[16], bq[16];
    int t = threadIdx.x;
    int blk = blockIdx.x;
    int h = blk >> 9;
    if (t < 32) {
        float m = g_s2[t] * (1.f / 131072.f);
        float var = g_s2[32 + t] * (1.f / 131072.f) - m * m;
        sm[t] = m; sr[t] = 1.0f / sqrtf(var + 1e-5f);
        sg[t] = gg[t]; sb[t] = be[t];
    }
    if (t < 16) { bs[t] = 0.f; bq[t] = 0.f; }
    if (t < 256) {
        int cpl = t & 7, ci = t >> 3;
        int co = 2 * (8 * h + cpl);
        ws2[t] = pk(w[co * 32 + ci], w[(co + 1) * 32 + ci]);
    }
    __syncthreads();
    int pos = (blk & 511) * 256 + t;
    int xy = pos & 4095, n = pos >> 12;
    const float* tin = g_t2 + ((size_t)n << 17) + xy;
    float raw[32];
#pragma unroll
    for (int ci = 0; ci < 32; ci++) raw[ci] = tin[(size_t)ci << 12];
    ull acc[8];
#pragma unroll
    for (int cpl = 0; cpl < 8; cpl++)
        acc[cpl] = pk(b[2 * (8 * h + cpl)], b[2 * (8 * h + cpl) + 1]);
#pragma unroll
    for (int ci = 0; ci < 32; ci++) {
        float vv = bnrelu(raw[ci], sg[ci], sm[ci], sr[ci], sb[ci]);
        ull vp = pk(vv, vv);
        const ulonglong2* qw = (const ulonglong2*)(ws2 + (ci << 3));
#pragma unroll
        for (int j = 0; j < 4; j++) {
            ulonglong2 a2 = qw[j];
            acc[2 * j]     = ffma2(vp, a2.x, acc[2 * j]);
            acc[2 * j + 1] = ffma2(vp, a2.y, acc[2 * j + 1]);
        }
    }
    float* to = g_t3 + ((size_t)n << 17) + xy;
#pragma unroll
    for (int cpl = 0; cpl < 8; cpl++) {
        int co = 2 * (8 * h + cpl);
        float a0, a1; upk(acc[cpl], a0, a1);
        to[(size_t)co << 12] = a0;
        to[(size_t)(co + 1) << 12] = a1;
        float s0 = a0, q0 = a0 * a0, s1 = a1, q1 = a1 * a1;
        WARP_RED2(s0, q0)
        WARP_RED2(s1, q1)
        if ((t & 31) == 0) {
            atomicAdd(&bs[2 * cpl], s0);     atomicAdd(&bq[2 * cpl], q0);
            atomicAdd(&bs[2 * cpl + 1], s1); atomicAdd(&bq[2 * cpl + 1], q1);
        }
    }
    __syncthreads();
    if (t < 16)      atomicAdd(&g_s3[16 * h + t], bs[t]);
    else if (t < 32) atomicAdd(&g_s3[32 + 16 * h + (t - 16)], bq[t - 16]);
}

// ---------- K4: bn3 -> z_e, VQ argmin, z_q, dec conv1 + stats4 ----------
__global__ void __launch_bounds__(256) k_vq(const float* __restrict__ emb,
                                            const float* __restrict__ gg,
                                            const float* __restrict__ be,
                                            const float* __restrict__ dw,
                                            const float* __restrict__ db,
                                            float* __restrict__ ze,
                                            float* __restrict__ zq,
                                            float* __restrict__ lat) {
    extern __shared__ unsigned char smraw[];
    ull* pe  = (ull*)smraw;          // 8192
    ull* pE  = pe + 8192;            // 256
    ull* dwp = pE + 256;             // 512
    ull* dbp = dwp + 512;            // 16
    float* sm3 = (float*)(dbp + 16);
    float* sr3 = sm3 + 32; float* sg3 = sr3 + 32; float* sb3 = sg3 + 32;
    float* bs = sb3 + 32; float* bq = bs + 32;
    int t = threadIdx.x;

    for (int e = t; e < 8192; e += 256) {
        int k = e & 31, p = e >> 5;
        pe[e] = pk(emb[(2 * p) * 32 + k], emb[(2 * p + 1) * 32 + k]);
    }
    {
        int p = t;
        float e0 = 0.f, e1 = 0.f;
#pragma unroll 8
        for (int k = 0; k < 32; k++) {
            float a = emb[(2 * p) * 32 + k];
            float c = emb[(2 * p + 1) * 32 + k];
            e0 = __fadd_rn(e0, __fmul_rn(a, a));
            e1 = __fadd_rn(e1, __fmul_rn(c, c));
        }
        pE[p] = pk(e0, e1);
    }
    for (int e = t; e < 512; e += 256) {
        int cp = e & 15, ci = e >> 4;
        dwp[e] = pk(dw[(2 * cp) * 32 + ci], dw[(2 * cp + 1) * 32 + ci]);
    }
    if (t < 16) dbp[t] = pk(db[2 * t], db[2 * t + 1]);
    if (t < 32) {
        float m = g_s3[t] * (1.f / 131072.f);
        float var = g_s3[32 + t] * (1.f / 131072.f) - m * m;
        sm3[t] = m; sr3[t] = 1.0f / sqrtf(var + 1e-5f);
        sg3[t] = gg[t]; sb3[t] = be[t];
        bs[t] = 0.f; bq[t] = 0.f;
    }
    __syncthreads();

    int pos = blockIdx.x * 256 + t;
    int xy = pos & 4095, n = pos >> 12;

    float raw[32];
#pragma unroll
    for (int k = 0; k < 32; k++)
        raw[k] = g_t3[(((size_t)(n << 5) + k) << 12) + xy];

    ull zp[32];
    float S = 0.f;
#pragma unroll
    for (int k = 0; k < 32; k++) {
        float zb = __fadd_rn(__fmul_rn(__fmul_rn(sg3[k], __fsub_rn(raw[k], sm3[k])), sr3[k]), sb3[k]);
        ze[(((size_t)(n << 5) + k) << 12) + xy] = zb;
        S = __fadd_rn(S, __fmul_rn(zb, zb));
        zp[k] = pk(zb, zb);
    }

    float best = 3.402823466e38f;
    int bi = 0;
#pragma unroll 1
    for (int q = 0; q < 256; q += 2) {
        const ulonglong2* e0 = (const ulonglong2*)(pe + (q << 5));
        const ulonglong2* e1 = (const ulonglong2*)(pe + ((q + 1) << 5));
        ull a0 = 0ull, a1 = 0ull;
#pragma unroll
        for (int kk = 0; kk < 16; kk++) {
            ulonglong2 w0 = e0[kk];
            ulonglong2 w1 = e1[kk];
            a0 = ffma2(zp[2 * kk], w0.x, a0);
            a1 = ffma2(zp[2 * kk], w1.x, a1);
            a0 = ffma2(zp[2 * kk + 1], w0.y, a0);
            a1 = ffma2(zp[2 * kk + 1], w1.y, a1);
        }
        float m0, m1, m2, m3, E0, E1, E2, E3;
        upk(a0, m0, m1); upk(a1, m2, m3);
        upk(pE[q], E0, E1); upk(pE[q + 1], E2, E3);
        float d;
        d = __fadd_rn(__fsub_rn(S, __fadd_rn(m0, m0)), E0); if (d < best) { best = d; bi = 2 * q; }
        d = __fadd_rn(__fsub_rn(S, __fadd_rn(m1, m1)), E1); if (d < best) { best = d; bi = 2 * q + 1; }
        d = __fadd_rn(__fsub_rn(S, __fadd_rn(m2, m2)), E2); if (d < best) { best = d; bi = 2 * q + 2; }
        d = __fadd_rn(__fsub_rn(S, __fadd_rn(m3, m3)), E3); if (d < best) { best = d; bi = 2 * q + 3; }
    }

    lat[pos] = (float)bi;

    const float* pef = (const float*)pe;
    int zbase = (((bi >> 1) << 5) << 1) + (bi & 1);
    ull acc[16];
#pragma unroll
    for (int cp = 0; cp < 16; cp++) acc[cp] = dbp[cp];
#pragma unroll 4
    for (int ci = 0; ci < 32; ci++) {
        float zv = pef[zbase + (ci << 1)];
        zq[(((size_t)(n << 5) + ci) << 12) + xy] = zv;
        ull vp = pk(zv, zv);
        const ulonglong2* qd = (const ulonglong2*)(dwp + (ci << 4));
#pragma unroll
        for (int j = 0; j < 8; j++) {
            ulonglong2 w2v = qd[j];
            acc[2 * j]     = ffma2(vp, w2v.x, acc[2 * j]);
            acc[2 * j + 1] = ffma2(vp, w2v.y, acc[2 * j + 1]);
        }
    }
    float* to = g_t4 + ((size_t)n << 17) + xy;
#pragma unroll
    for (int cp = 0; cp < 16; cp++) {
        float a0, a1; upk(acc[cp], a0, a1);
        to[(size_t)(2 * cp) << 12] = a0;
        to[(size_t)(2 * cp + 1) << 12] = a1;
        float s0 = a0, q0 = a0 * a0, s1 = a1, q1 = a1 * a1;
        WARP_RED2(s0, q0)
        WARP_RED2(s1, q1)
        if ((t & 31) == 0) {
            atomicAdd(&bs[2 * cp], s0);     atomicAdd(&bq[2 * cp], q0);
            atomicAdd(&bs[2 * cp + 1], s1); atomicAdd(&bq[2 * cp + 1], q1);
        }
    }
    __syncthreads();
    if (t < 32)      atomicAdd(&g_s4[t], bs[t]);
    else if (t < 64) atomicAdd(&g_s4[t], bq[t - 32]);
}

// ---------- K5: bn4+relu -> convT1 32->16 with SMEM staging, + stats5 ----------
__global__ void __launch_bounds__(256) k_convT1(const float* __restrict__ w,
                                                const float* __restrict__ b,
                                                const float* __restrict__ gg,
                                                const float* __restrict__ be) {
    extern __shared__ unsigned char dsm[];
    ull* wp = (ull*)dsm;                     // 4096
    ull* bp = wp + 4096;                     // 8
    float* sin_ = (float*)(bp + 8);          // 32*3*66 = 6336
    float* sm = sin_ + 6336; float* sr = sm + 32;
    float* sg = sr + 32;     float* sb = sg + 32;
    float* bs = sb + 32;     float* bq = bs + 16;
    int t = threadIdx.x;
    if (t < 32) {
        float m = g_s4[t] * (1.f / 131072.f);
        float var = g_s4[32 + t] * (1.f / 131072.f) - m * m;
        sm[t] = m; sr[t] = 1.0f / sqrtf(var + 1e-5f);
        sg[t] = gg[t]; sb[t] = be[t];
    }
    if (t < 16) { bs[t] = 0.f; bq[t] = 0.f; }
    if (t < 8)  bp[t] = pk(b[2 * t], b[2 * t + 1]);
    for (int e = t; e < 4096; e += 256) {
        int cp = e & 7, tap = (e >> 3) & 15, ci = e >> 7;
        wp[e] = pk(w[ci * 256 + (2 * cp) * 16 + tap],
                   w[ci * 256 + (2 * cp + 1) * 16 + tap]);
    }
    if (t < 96) { sin_[t * 66] = 0.f; sin_[t * 66 + 65] = 0.f; }
    __syncthreads();                          // bn coefs + pads ready

    int blk = blockIdx.x;
    int m_ = blk & 63, n = blk >> 6;          // oy in {2m_, 2m_+1}
#pragma unroll 4
    for (int e = t; e < 6144; e += 256) {     // 32 ci x 3 rows x 64 cols
        int ci = e / 192;
        int rem = e - ci * 192;
        int j = rem >> 6, ix = rem & 63;
        int iy = m_ - 1 + j;
        float f = 0.f;
        if (iy >= 0 && iy <= 63) {
            float rv = g_t4[(((size_t)(n << 5) + ci) << 12) + (iy << 6) + ix];
            f = bnrelu(rv, sg[ci], sm[ci], sr[ci], sb[ci]);
        }
        sin_[(ci * 3 + j) * 66 + 1 + ix] = f;
    }
    __syncthreads();

    int r = t >> 7, ox = t & 127, oy = 2 * m_ + r;
    int ja = 1 + r, jb = r;                   // rows iya=m_+r, iyb=m_-1+r
    int iya = (oy + 1) >> 1;
    int kya = oy - 2 * iya + 1, kyb = kya + 2;
    int ixa = (ox + 1) >> 1, kxa = ox - 2 * ixa + 1, ixb = ixa - 1, kxb = kxa + 2;
    int taa = kya * 4 + kxa, tab = kya * 4 + kxb, tba = kyb * 4 + kxa, tbb = kyb * 4 + kxb;
    ull acc[8];
#pragma unroll
    for (int cp = 0; cp < 8; cp++) acc[cp] = bp[cp];
#pragma unroll 1
    for (int ci = 0; ci < 32; ci++) {
        const float* ra = sin_ + (ci * 3 + ja) * 66;
        const float* rb = sin_ + (ci * 3 + jb) * 66;
        float f00 = ra[ixa + 1], f01 = ra[ixb + 1];
        float f10 = rb[ixa + 1], f11 = rb[ixb + 1];
        ull p00 = pk(f00, f00), p01 = pk(f01, f01), p10 = pk(f10, f10), p11 = pk(f11, f11);
        const ull* wb0 = wp + (ci << 7);
        const ulonglong2* wA = (const ulonglong2*)(wb0 + (taa << 3));
        const ulonglong2* wB = (const ulonglong2*)(wb0 + (tab << 3));
        const ulonglong2* wC = (const ulonglong2*)(wb0 + (tba << 3));
        const ulonglong2* wD = (const ulonglong2*)(wb0 + (tbb << 3));
#pragma unroll
        for (int j = 0; j < 4; j++) {
            ulonglong2 a2 = wA[j], b2 = wB[j], c2 = wC[j], d2 = wD[j];
            acc[2 * j]     = ffma2(p00, a2.x, acc[2 * j]);
            acc[2 * j + 1] = ffma2(p00, a2.y, acc[2 * j + 1]);
            acc[2 * j]     = ffma2(p01, b2.x, acc[2 * j]);
            acc[2 * j + 1] = ffma2(p01, b2.y, acc[2 * j + 1]);
            acc[2 * j]     = ffma2(p10, c2.x, acc[2 * j]);
            acc[2 * j + 1] = ffma2(p10, c2.y, acc[2 * j + 1]);
            acc[2 * j]     = ffma2(p11, d2.x, acc[2 * j]);
            acc[2 * j + 1] = ffma2(p11, d2.y, acc[2 * j + 1]);
        }
    }
    float* to = g_t5 + ((size_t)n << 18) + (oy << 7) + ox;
#pragma unroll
    for (int cp = 0; cp < 8; cp++) {
        float a0, a1; upk(acc[cp], a0, a1);
        to[(size_t)(2 * cp) << 14] = a0;
        to[(size_t)(2 * cp + 1) << 14] = a1;
        float s0 = a0, q0 = a0 * a0, s1 = a1, q1 = a1 * a1;
        WARP_RED2(s0, q0)
        WARP_RED2(s1, q1)
        if ((t & 31) == 0) {
            atomicAdd(&bs[2 * cp], s0);     atomicAdd(&bq[2 * cp], q0);
            atomicAdd(&bs[2 * cp + 1], s1); atomicAdd(&bq[2 * cp + 1], q1);
        }
    }
    __syncthreads();
    if (t < 16)      atomicAdd(&g_s5[t], bs[t]);
    else if (t < 32) atomicAdd(&g_s5[t], bq[t - 16]);
}

// ---------- K6: bn5+relu -> convT2 16->30 with SMEM staging ----------
__global__ void __launch_bounds__(256) k_convT2(const float* __restrict__ w,
                                                const float* __restrict__ b,
                                                const float* __restrict__ gg,
                                                const float* __restrict__ be,
                                                float* __restrict__ out) {
    extern __shared__ unsigned char dsm[];
    ull* wp = (ull*)dsm;                     // 4096
    ull* bp = wp + 4096;                     // 16
    float* sin_ = (float*)(bp + 16);         // 16*2*130 = 4160
    float* sm = sin_ + 4160; float* sr = sm + 16;
    float* sg = sr + 16;     float* sb = sg + 16;
    int t = threadIdx.x;
    if (t < 16) {
        float m = g_s5[t] * (1.f / 524288.f);
        float var = g_s5[16 + t] * (1.f / 524288.f) - m * m;
        sm[t] = m; sr[t] = 1.0f / sqrtf(var + 1e-5f);
        sg[t] = gg[t]; sb[t] = be[t];
    }
    if (t < 16) bp[t] = (t < 15) ? pk(b[2 * t], b[2 * t + 1]) : pk(0.f, 0.f);
    for (int e = t; e < 4096; e += 256) {
        int cp = e & 15, tap = (e >> 4) & 15, ci = e >> 8;
        wp[e] = (cp < 15) ? pk(w[ci * 480 + (2 * cp) * 16 + tap],
                               w[ci * 480 + (2 * cp + 1) * 16 + tap])
                          : pk(0.f, 0.f);
    }
    if (t < 32) { int q = t; sin_[q * 130] = 0.f; sin_[q * 130 + 129] = 0.f; }
    __syncthreads();

    int blk = blockIdx.x;
    int oy = blk & 255, n = blk >> 8;
    int iya = (oy + 1) >> 1, iyb = iya - 1;
    bool vya = iya <= 127, vyb = iyb >= 0;
#pragma unroll 4
    for (int e = t; e < 4096; e += 256) {     // 16 ci x 2 rows x 128 cols
        int ix = e & 127, rr = (e >> 7) & 1, ci = e >> 8;
        int iy = rr ? iyb : iya;
        bool v = rr ? vyb : vya;
        float f = 0.f;
        if (v) {
            float rv = g_t5[(((size_t)(n << 4) + ci) << 14) + (iy << 7) + ix];
            f = bnrelu(rv, sg[ci], sm[ci], sr[ci], sb[ci]);
        }
        sin_[(ci * 2 + rr) * 130 + 1 + ix] = f;
    }
    __syncthreads();

    int ox = t;
    int kya = oy - 2 * iya + 1, kyb = kya + 2;
    int ixa = (ox + 1) >> 1, kxa = ox - 2 * ixa + 1, ixb = ixa - 1, kxb = kxa + 2;
    int taa = kya * 4 + kxa, tab = kya * 4 + kxb, tba = kyb * 4 + kxa, tbb = kyb * 4 + kxb;
    ull acc[16];
#pragma unroll
    for (int cp = 0; cp < 16; cp++) acc[cp] = bp[cp];
#pragma unroll 1
    for (int ci = 0; ci < 16; ci++) {
        const float* r0 = sin_ + (ci * 2) * 130;      // iya row
        const float* r1 = r0 + 130;                    // iyb row
        float f00 = r0[ixa + 1], f01 = r0[ixb + 1];
        float f10 = r1[ixa + 1], f11 = r1[ixb + 1];
        ull p00 = pk(f00, f00), p01 = pk(f01, f01), p10 = pk(f10, f10), p11 = pk(f11, f11);
        const ull* wb0 = wp + (ci << 8);
        const ulonglong2* wA = (const ulonglong2*)(wb0 + (taa << 4));
        const ulonglong2* wB = (const ulonglong2*)(wb0 + (tab << 4));
        const ulonglong2* wC = (const ulonglong2*)(wb0 + (tba << 4));
        const ulonglong2* wD = (const ulonglong2*)(wb0 + (tbb << 4));
#pragma unroll
        for (int j = 0; j < 8; j++) {
            ulonglong2 a2 = wA[j], b2 = wB[j], c2 = wC[j], d2 = wD[j];
            acc[2 * j]     = ffma2(p00, a2.x, acc[2 * j]);
            acc[2 * j + 1] = ffma2(p00, a2.y, acc[2 * j + 1]);
            acc[2 * j]     = ffma2(p01, b2.x, acc[2 * j]);
            acc[2 * j + 1] = ffma2(p01, b2.y, acc[2 * j + 1]);
            acc[2 * j]     = ffma2(p10, c2.x, acc[2 * j]);
            acc[2 * j + 1] = ffma2(p10, c2.y, acc[2 * j + 1]);
            acc[2 * j]     = ffma2(p11, d2.x, acc[2 * j]);
            acc[2 * j + 1] = ffma2(p11, d2.y, acc[2 * j + 1]);
        }
    }
    float* to = out + (size_t)n * (30 * 65536) + (oy << 8) + ox;
#pragma unroll
    for (int cp = 0; cp < 15; cp++) {
        float a0, a1; upk(acc[cp], a0, a1);
        to[(size_t)(2 * cp) << 16] = a0;
        to[(size_t)(2 * cp + 1) << 16] = a1;
    }
}

// ---------- host ----------
extern "C" void kernel_launch(void* const* d_in, const int* in_sizes, int n_in,
                              void* d_out, int out_size) {
    const float* x    = (const float*)d_in[0];
    const float* w1   = (const float*)d_in[1];
    const float* b1   = (const float*)d_in[2];
    const float* g1   = (const float*)d_in[3];
    const float* be1  = (const float*)d_in[4];
    const float* w2   = (const float*)d_in[5];
    const float* b2   = (const float*)d_in[6];
    const float* g2   = (const float*)d_in[7];
    const float* be2  = (const float*)d_in[8];
    const float* w3   = (const float*)d_in[9];
    const float* b3   = (const float*)d_in[10];
    const float* g3   = (const float*)d_in[11];
    const float* be3  = (const float*)d_in[12];
    const float* emb  = (const float*)d_in[13];
    const float* dw1  = (const float*)d_in[14];
    const float* db1  = (const float*)d_in[15];
    const float* dg1  = (const float*)d_in[16];
    const float* dbe1 = (const float*)d_in[17];
    const float* dtw1 = (const float*)d_in[18];
    const float* dtb1 = (const float*)d_in[19];
    const float* dg2  = (const float*)d_in[20];
    const float* dbe2 = (const float*)d_in[21];
    const float* dtw2 = (const float*)d_in[22];
    const float* dtb2 = (const float*)d_in[23];

    float* out = (float*)d_out;
    const long long XT = 62914560LL, ZE = 4194304LL, LA = 131072LL;
    float *xt = out, *ze, *zq, *lat;
    if ((long long)out_size >= XT + 2 * ZE + LA) {
        ze  = out + XT;
        zq  = out + XT + ZE;
        lat = out + XT + 2 * ZE;
    } else {
        void* p;
        cudaGetSymbolAddress(&p, g_zefb);  ze  = (float*)p;
        cudaGetSymbolAddress(&p, g_zqfb);  zq  = (float*)p;
        cudaGetSymbolAddress(&p, g_latfb); lat = (float*)p;
    }

    cudaFuncSetAttribute(k_vq, cudaFuncAttributeMaxDynamicSharedMemorySize, 73728);
    cudaFuncSetAttribute(k_convT1, cudaFuncAttributeMaxDynamicSharedMemorySize, 58816);
    cudaFuncSetAttribute(k_convT2, cudaFuncAttributeMaxDynamicSharedMemorySize, 49792);

    k_zero<<<1, 256>>>();
    k_conv1<<<2048, 256>>>(x, w1, b1);
    k_conv2<<<1024, 256>>>(w2, b2, g1, be1);
    k_conv1x1a<<<1024, 256>>>(w3, b3, g2, be2);
    k_vq<<<512, 256, 73728>>>(emb, g3, be3, dw1, db1, ze, zq, lat);
    k_convT1<<<2048, 256, 58816>>>(dtw1, dtb1, dg1, dbe1);
    k_convT2<<<8192, 256, 49792>>>(dtw2, dtb2, dg2, dbe2, xt);
}